// round 14
// baseline (speedup 1.0000x reference)
#include <cuda_runtime.h>
#include <math.h>
#include <cstdint>

#define BB 8
#define CIN 512
#define HH 64
#define WW 64
#define HWP 4096          // 64*64
#define NA 36864          // anchors per batch = 4096*9
#define NSORT 65536
#define NPRE 6000
#define NPOST 300

// output layout (floats)
#define OFF_CLS 0ull
#define OFF_LOC 589824ull
#define OFF_ROI 1769472ull
#define OFF_IDX 1779072ull

#define NEGINF (__int_as_float(0xff800000))

typedef unsigned long long ull;

// ---------------- packed f32x2 helpers (bitwise-identical IEEE fp32) ---------
__device__ __forceinline__ ull pack2(float x, float y) {
    ull r;
    asm("mov.b64 %0, {%1, %2};" : "=l"(r) : "f"(x), "f"(y));
    return r;
}
__device__ __forceinline__ float2 unpack2(ull v) {
    float2 r;
    asm("mov.b64 {%0, %1}, %2;" : "=f"(r.x), "=f"(r.y) : "l"(v));
    return r;
}
__device__ __forceinline__ void ffma2(ull& d, ull a, ull b) {
    asm("fma.rn.f32x2 %0, %1, %2, %0;" : "+l"(d) : "l"(a), "l"(b));
}

__device__ __forceinline__ uint32_t smem_u32(const void* p) {
    uint32_t a;
    asm("{ .reg .u64 t; cvta.to.shared.u64 t, %1; cvt.u32.u64 %0, t; }"
        : "=r"(a) : "l"(p));
    return a;
}
#define CP_COMMIT() asm volatile("cp.async.commit_group;" ::: "memory")
#define CP_WAIT1()  asm volatile("cp.async.wait_group 1;" ::: "memory")
#define CP_WAIT0()  asm volatile("cp.async.wait_group 0;" ::: "memory")

__device__ __forceinline__ void cp4(uint32_t dst, const float* src, bool ok) {
    asm volatile("cp.async.ca.shared.global [%0], [%1], 4, %2;"
                 :: "r"(dst), "l"(src), "r"(ok ? 4u : 0u) : "memory");
}

// ---------------- scratch (static device globals; no allocation) -------------
static __device__ float g_h[(size_t)BB * CIN * HWP];            // 64 MB conv output
static __device__ float g_wt[(size_t)CIN * 9 * CIN];            // transposed conv weights
static __device__ float g_roi[(size_t)BB * NA * 4];             // clipped boxes
static __device__ float g_score[(size_t)BB * NA];               // scores (-inf if invalid)
static __device__ ull g_keys[(size_t)BB * NSORT];               // sort keys (padded)
static __device__ float g_nbox[(size_t)BB * NPRE * 4];          // gathered top-6000 boxes

// anchor base half-heights / half-widths (float32 of the np.float64 math)
__constant__ float c_h2[9] = {
    45.254833995939045f, 90.50966799187809f, 181.01933598375618f,
    64.0f, 128.0f, 256.0f,
    90.50966799187809f, 181.01933598375618f, 362.03867196751236f};
__constant__ float c_w2[9] = {
    90.50966799187809f, 181.01933598375618f, 362.03867196751236f,
    64.0f, 128.0f, 256.0f,
    45.254833995939045f, 90.50966799187809f, 181.01933598375618f};

// ---------------- 0: weight transpose  [oc][ic][3][3] -> [ic][k][oc] ---------
__global__ void wtrans_kernel(const float* __restrict__ w) {
    int idx = blockIdx.x * blockDim.x + threadIdx.x;
    if (idx >= CIN * CIN * 9) return;
    int kk = idx % 9;
    int ic = (idx / 9) % CIN;
    int oc = idx / (9 * CIN);
    g_wt[((size_t)ic * 9 + kk) * CIN + oc] = w[idx];
}

// ---------------- 1: 3x3 conv + bias + relu --------------------------------
// R13 compute chain (bitwise-identical FFMA2 accumulation) with DUPLICATED
// input smem: each staged input value stored as an adjacent (v,v) pair, so the
// compute loop loads ready-packed f32x2 operands via 5 LDS.128 instead of
// 3 LDS + 10 pack MOVs (aux issues per (ic,ky): 19 -> 11; every aux issue is
// a stolen FMA slot at 1 issue/cyc/SMSP).
// Input row: 66 duplicated pairs, padded to 136 words (16B-aligned pairs).
#define IN_WORDS (8 * 6 * 136)         // 6528 (duplicated pairs)
#define W_WORDS (8 * 9 * 64)           // 4608
#define BUF_WORDS (IN_WORDS + W_WORDS) // 11136
#define CONV_SMEM (2 * BUF_WORDS * 4)  // 89088 bytes (x2 CTAs = 174 KB/SM)

__global__ __launch_bounds__(256, 2) void conv3x3_kernel(
    const float* __restrict__ x, const float* __restrict__ bias) {
    extern __shared__ float sm[];
    const int octile = blockIdx.x;   // 0..7   (oc base = octile*64)
    const int y0 = blockIdx.y * 4;   // rows y0..y0+3
    const int b = blockIdx.z;        // 0..7
    const int tid = threadIdx.x;
    const int lane = tid & 31;
    const int ty = tid >> 5;         // warp id = oc subgroup 0..7
    const int r_out = lane >> 3;     // 0..3 row within block
    const int X0 = (lane & 7) * 8;   // x base, 8 px per thread

    const float* xb = x + (size_t)b * CIN * HWP;

    // stage chunk (8 input channels starting at icg) into buffer buf
    auto stage = [&](int buf, int icg) {
        float* s_in = sm + buf * BUF_WORDS;
        float* s_wt = s_in + IN_WORDS;
        // inputs: 48 halo'd rows (8 ic x 6 rows) x 66 cols, each value written
        // TWICE (duplicated pair). Warp ty owns rows ty, ty+8, ..., ty+40.
#pragma unroll
        for (int j = 0; j < 6; j++) {
            int row = ty + 8 * j;        // 0..47
            int ic = row / 6;            // const-div (mul-shift)
            int r = row - ic * 6;        // 0..5
            int gy = y0 + r - 1;
            bool rowok = ((unsigned)gy < 64u);
            const float* srow = xb + (size_t)(icg + ic) * HWP + gy * 64;
            uint32_t drow = smem_u32(&s_in[(ic * 6 + r) * 136]);
            {
                int gx = lane - 1;                       // xx = lane
                bool ok = rowok && (gx >= 0);
                const float* src = ok ? (srow + gx) : xb;
                cp4(drow + (2 * lane) * 4, src, ok);
                cp4(drow + (2 * lane + 1) * 4, src, ok);
            }
            {
                int gx = lane + 31;                      // xx = lane+32 (<64 always)
                const float* src = rowok ? (srow + gx) : xb;
                cp4(drow + (2 * (lane + 32)) * 4, src, rowok);
                cp4(drow + (2 * (lane + 32) + 1) * 4, src, rowok);
            }
            if (lane < 2) {
                int gx = lane + 63;                      // xx = lane+64
                bool ok = rowok && (gx < 64);
                const float* src = ok ? (srow + gx) : xb;
                cp4(drow + (2 * (lane + 64)) * 4, src, ok);
                cp4(drow + (2 * (lane + 64) + 1) * 4, src, ok);
            }
        }
        // weights: 8 ic x 9 taps x 64 oc via 16B cp.async (1152 chunks)
        const float* wsrc = g_wt + (size_t)icg * 9 * CIN + octile * 64;
#pragma unroll
        for (int j = 0; j < 5; j++) {
            int t = tid + j * 256;
            if (t < 1152) {
                int c4 = t & 15;
                int kk = (t >> 4) % 9;
                int ic = t / 144;
                const float* src = wsrc + (size_t)(ic * 9 + kk) * CIN + c4 * 4;
                uint32_t dst = smem_u32(&s_wt[(ic * 9 + kk) * 64 + c4 * 4]);
                asm volatile("cp.async.cg.shared.global [%0], [%1], 16;"
                             :: "r"(dst), "l"(src) : "memory");
            }
        }
    };

    // acc2[g][i]: packed (acc[oc=2g], acc[oc=2g+1]) for px i
    ull acc2[4][8];
#pragma unroll
    for (int g = 0; g < 4; g++)
#pragma unroll
        for (int i = 0; i < 8; i++) acc2[g][i] = pack2(0.f, 0.f);

    stage(0, 0);
    CP_COMMIT();

    for (int s = 0; s < 64; s++) {
        if (s + 1 < 64) {
            stage((s + 1) & 1, (s + 1) * 8);
            CP_COMMIT();
            CP_WAIT1();
        } else {
            CP_WAIT0();
        }
        __syncthreads();

        const float* s_in = sm + (s & 1) * BUF_WORDS;
        const float* s_wt = s_in + IN_WORDS;

#pragma unroll
        for (int ic = 0; ic < 8; ic++) {
#pragma unroll
            for (int ky = 0; ky < 3; ky++) {
                // 10 packed cols X0..X0+9 via 5 LDS.128 (pair idx X0, 64B-aligned)
                const ulonglong2* ip =
                    (const ulonglong2*)&s_in[(ic * 6 + r_out + ky) * 136 + X0 * 2];
                ull xp[10];
                {
                    ulonglong2 p0 = ip[0];
                    ulonglong2 p1 = ip[1];
                    ulonglong2 p2 = ip[2];
                    ulonglong2 p3 = ip[3];
                    ulonglong2 p4 = ip[4];
                    xp[0] = p0.x; xp[1] = p0.y;
                    xp[2] = p1.x; xp[3] = p1.y;
                    xp[4] = p2.x; xp[5] = p2.y;
                    xp[6] = p3.x; xp[7] = p3.y;
                    xp[8] = p4.x; xp[9] = p4.y;
                }
#pragma unroll
                for (int kx = 0; kx < 3; kx++) {
                    // 8 oc weights via two 128-bit loads (warp-uniform addr)
                    const ulonglong2* wp =
                        (const ulonglong2*)&s_wt[(ic * 9 + ky * 3 + kx) * 64 + ty * 8];
                    ulonglong2 wv0 = wp[0];
                    ulonglong2 wv1 = wp[1];
#pragma unroll
                    for (int i = 0; i < 8; i++) {
                        ffma2(acc2[0][i], xp[i + kx], wv0.x);
                        ffma2(acc2[1][i], xp[i + kx], wv0.y);
                        ffma2(acc2[2][i], xp[i + kx], wv1.x);
                        ffma2(acc2[3][i], xp[i + kx], wv1.y);
                    }
                }
            }
        }
        __syncthreads();
    }

    const int ocbase = octile * 64 + ty * 8;
    const int yrow = y0 + r_out;
#pragma unroll
    for (int g = 0; g < 4; g++) {
        float bv0 = bias[ocbase + 2 * g];
        float bv1 = bias[ocbase + 2 * g + 1];
        float r0[8], r1[8];
#pragma unroll
        for (int i = 0; i < 8; i++) {
            float2 u = unpack2(acc2[g][i]);
            r0[i] = fmaxf(u.x + bv0, 0.f);
            r1[i] = fmaxf(u.y + bv1, 0.f);
        }
        float* d0 = &g_h[((size_t)(b * CIN + ocbase + 2 * g)) * HWP + yrow * WW + X0];
        float* d1 = &g_h[((size_t)(b * CIN + ocbase + 2 * g + 1)) * HWP + yrow * WW + X0];
        *(float4*)(d0)     = make_float4(r0[0], r0[1], r0[2], r0[3]);
        *(float4*)(d0 + 4) = make_float4(r0[4], r0[5], r0[6], r0[7]);
        *(float4*)(d1)     = make_float4(r1[0], r1[1], r1[2], r1[3]);
        *(float4*)(d1 + 4) = make_float4(r1[4], r1[5], r1[6], r1[7]);
    }
}

// ---------------- 2: heads (1x1 convs) + proposal prep -----------------------
__global__ __launch_bounds__(128) void heads_kernel(
    const float* __restrict__ loc_w, const float* __restrict__ loc_b,
    const float* __restrict__ cls_w, const float* __restrict__ cls_b,
    const int* __restrict__ imh, const int* __restrict__ imw,
    float* __restrict__ out) {
    const int b = blockIdx.x >> 5;
    const int p = ((blockIdx.x & 31) << 7) + threadIdx.x;  // 0..4095

    __shared__ float s_w[64][56];  // padded to 56 for 8B alignment of pairs

    ull acc2[27];
#pragma unroll
    for (int m = 0; m < 27; m++) acc2[m] = pack2(0.f, 0.f);

    const float* hb = g_h + (size_t)b * CIN * HWP + p;

    for (int icg = 0; icg < CIN; icg += 64) {
        __syncthreads();
        for (int t = threadIdx.x; t < 64 * 54; t += 128) {
            int m = t % 54;
            int ic = t / 54;
            float wv = (m < 36) ? loc_w[m * CIN + icg + ic]
                                : cls_w[(m - 36) * CIN + icg + ic];
            s_w[ic][m] = wv;
        }
        __syncthreads();
        for (int ic = 0; ic < 64; ic++) {
            float hv = hb[(size_t)(icg + ic) * HWP];
            ull hp = pack2(hv, hv);
            const ull* wrow = (const ull*)&s_w[ic][0];
#pragma unroll
            for (int m = 0; m < 27; m++) ffma2(acc2[m], hp, wrow[m]);
        }
    }

    float acc[54];
#pragma unroll
    for (int m = 0; m < 27; m++) {
        float2 u = unpack2(acc2[m]);
        acc[2 * m] = u.x;
        acc[2 * m + 1] = u.y;
    }

    const float fh = (float)(*imh);
    const float fw = (float)(*imw);
    const int py = p >> 6, px = p & 63;
    const float sy = (float)py * 16.0f;
    const float sx = (float)px * 16.0f;

    const size_t cls_base = OFF_CLS + ((size_t)b * NA + (size_t)p * 9) * 2;
    const size_t loc_base = OFF_LOC + ((size_t)b * NA + (size_t)p * 9) * 4;

#pragma unroll
    for (int a = 0; a < 9; a++) {
        float dy = acc[4 * a + 0] + loc_b[4 * a + 0];
        float dx = acc[4 * a + 1] + loc_b[4 * a + 1];
        float dh = acc[4 * a + 2] + loc_b[4 * a + 2];
        float dw = acc[4 * a + 3] + loc_b[4 * a + 3];
        out[loc_base + a * 4 + 0] = dy;
        out[loc_base + a * 4 + 1] = dx;
        out[loc_base + a * 4 + 2] = dh;
        out[loc_base + a * 4 + 3] = dw;

        float v0 = acc[36 + 2 * a + 0] + cls_b[2 * a + 0];
        float v1 = acc[36 + 2 * a + 1] + cls_b[2 * a + 1];
        float c0 = 1.f / (1.f + expf(-v0));
        float c1 = 1.f / (1.f + expf(-v1));
        out[cls_base + a * 2 + 0] = c0;
        out[cls_base + a * 2 + 1] = c1;

        // anchor decode + clip + min-size filter
        float a0 = -c_h2[a] + sy;
        float a1 = -c_w2[a] + sx;
        float a2 = c_h2[a] + sy;
        float a3 = c_w2[a] + sx;
        float hh = a2 - a0;
        float ww = a3 - a1;
        float cy = a0 + 0.5f * hh;
        float cx = a1 + 0.5f * ww;
        cy = cy + dy * hh;
        cx = cx + dx * ww;
        hh = hh * expf(dh);
        ww = ww * expf(dw);
        float r0 = cy - 0.5f * hh;
        float r1 = cx - 0.5f * ww;
        float r2 = cy + 0.5f * hh;
        float r3 = cx + 0.5f * ww;
        r0 = fminf(fmaxf(r0, 0.f), fh);
        r1 = fminf(fmaxf(r1, 0.f), fw);
        r2 = fminf(fmaxf(r2, 0.f), fh);
        r3 = fminf(fmaxf(r3, 0.f), fw);
        float hs = r2 - r0;
        float ws = r3 - r1;
        bool valid = (hs >= 16.0f) && (ws >= 16.0f);
        float sc = valid ? c1 : NEGINF;

        int i = p * 9 + a;
        float4 rb;
        rb.x = r0; rb.y = r1; rb.z = r2; rb.w = r3;
        *(float4*)&g_roi[((size_t)b * NA + i) * 4] = rb;
        g_score[(size_t)b * NA + i] = sc;
        unsigned uu = __float_as_uint(sc);
        uu = (uu & 0x80000000u) ? ~uu : (uu | 0x80000000u);
        g_keys[(size_t)b * NSORT + i] =
            ((ull)uu << 32) | (unsigned)(0xFFFFFFFFu - (unsigned)i);
    }
    // padding keys (7 per thread: 4096*7 = 28672 = 65536-36864)
#pragma unroll
    for (int k2 = 0; k2 < 7; k2++)
        g_keys[(size_t)b * NSORT + NA + p * 7 + k2] = 0ull;
}

// ---------------- 3: bitonic sort, smem-tiled --------------------------------
#define TILE 4096

__global__ __launch_bounds__(1024) void sort_phase1_kernel() {
    __shared__ ull s[TILE];
    const int batch = blockIdx.x >> 4;
    const int tile = blockIdx.x & 15;
    ull* d = g_keys + (size_t)batch * NSORT + (size_t)tile * TILE;
    const int gbase = tile * TILE;

    for (int t = threadIdx.x; t < TILE; t += 1024) s[t] = d[t];
    __syncthreads();

    for (int k = 2; k <= TILE; k <<= 1) {
        for (int j = k >> 1; j > 0; j >>= 1) {
            for (int t = threadIdx.x; t < TILE; t += 1024) {
                int ixj = t ^ j;
                if (ixj > t) {
                    ull A = s[t];
                    ull Bv = s[ixj];
                    bool up = (((gbase + t) & k) == 0);
                    if (up ? (A > Bv) : (A < Bv)) {
                        s[t] = Bv;
                        s[ixj] = A;
                    }
                }
            }
            __syncthreads();
        }
    }
    for (int t = threadIdx.x; t < TILE; t += 1024) d[t] = s[t];
}

__global__ __launch_bounds__(256) void sort_gstep_kernel(int k, int j) {
    int idx = blockIdx.x * blockDim.x + threadIdx.x;
    int b = idx >> 16;
    int t = idx & (NSORT - 1);
    ull* d = g_keys + (size_t)b * NSORT;
    int ixj = t ^ j;
    if (ixj > t) {
        ull A = d[t];
        ull Bv = d[ixj];
        bool up = ((t & k) == 0);
        if (up ? (A > Bv) : (A < Bv)) {
            d[t] = Bv;
            d[ixj] = A;
        }
    }
}

__global__ __launch_bounds__(1024) void sort_sphase_kernel(int k) {
    __shared__ ull s[TILE];
    const int batch = blockIdx.x >> 4;
    const int tile = blockIdx.x & 15;
    ull* d = g_keys + (size_t)batch * NSORT + (size_t)tile * TILE;
    const int gbase = tile * TILE;

    for (int t = threadIdx.x; t < TILE; t += 1024) s[t] = d[t];
    __syncthreads();

    for (int j = TILE / 2; j > 0; j >>= 1) {
        for (int t = threadIdx.x; t < TILE; t += 1024) {
            int ixj = t ^ j;
            if (ixj > t) {
                ull A = s[t];
                ull Bv = s[ixj];
                bool up = (((gbase + t) & k) == 0);
                if (up ? (A > Bv) : (A < Bv)) {
                    s[t] = Bv;
                    s[ixj] = A;
                }
            }
        }
        __syncthreads();
    }
    for (int t = threadIdx.x; t < TILE; t += 1024) d[t] = s[t];
}

// ---------------- 4: per-batch NMS -------------------------------------------
__global__ __launch_bounds__(256) void nms_kernel(float* __restrict__ out) {
    __shared__ float ss[NPRE];
    __shared__ unsigned char smask[NPRE];
    __shared__ int s_pick;

    const int b = blockIdx.x;
    const ull* kb = g_keys + (size_t)b * NSORT;
    float* nb = g_nbox + (size_t)b * NPRE * 4;

    for (int t = threadIdx.x; t < NPRE; t += blockDim.x) {
        ull key = kb[NSORT - 1 - t];
        unsigned ai = 0xFFFFFFFFu - (unsigned)(key & 0xFFFFFFFFull);
        *(float4*)&nb[(size_t)t * 4] =
            *(const float4*)&g_roi[((size_t)b * NA + ai) * 4];
        ss[t] = g_score[(size_t)b * NA + ai];
        smask[t] = 0;
    }
    for (int t = threadIdx.x; t < NPOST; t += blockDim.x)
        out[OFF_IDX + (size_t)b * NPOST + t] = (float)b;
    __syncthreads();

    int ptr = 0;
    for (int pick = 0; pick < NPOST; pick++) {
        if (threadIdx.x == 0) {
            while (ptr < NPRE && smask[ptr]) ptr++;
            if (ptr < NPRE && ss[ptr] != NEGINF) {
                s_pick = ptr;
                smask[ptr] = 1;
            } else {
                s_pick = -1;
            }
        }
        __syncthreads();
        int p = s_pick;
        if (p < 0) {
            int rem = (NPOST - pick) * 4;
            for (int t = threadIdx.x; t < rem; t += blockDim.x)
                out[OFF_ROI + ((size_t)b * NPOST + pick) * 4 + t] = 0.f;
            break;
        }
        float4 pb = *(const float4*)&nb[(size_t)p * 4];
        if (threadIdx.x == 0) {
            out[OFF_ROI + ((size_t)b * NPOST + pick) * 4 + 0] = pb.x;
            out[OFF_ROI + ((size_t)b * NPOST + pick) * 4 + 1] = pb.y;
            out[OFF_ROI + ((size_t)b * NPOST + pick) * 4 + 2] = pb.z;
            out[OFF_ROI + ((size_t)b * NPOST + pick) * 4 + 3] = pb.w;
        }
        float parea = (pb.z - pb.x) * (pb.w - pb.y);
        for (int j = p + 1 + threadIdx.x; j < NPRE; j += blockDim.x) {
            if (!smask[j]) {
                float4 q = *(const float4*)&nb[(size_t)j * 4];
                float yy1 = fmaxf(q.x, pb.x);
                float xx1 = fmaxf(q.y, pb.y);
                float yy2 = fminf(q.z, pb.z);
                float xx2 = fminf(q.w, pb.w);
                float inter = fmaxf(yy2 - yy1, 0.f) * fmaxf(xx2 - xx1, 0.f);
                float qarea = (q.z - q.x) * (q.w - q.y);
                float iou = inter / (qarea + parea - inter + 1e-9f);
                if (iou > 0.7f) smask[j] = 1;
            }
        }
        __syncthreads();
    }
}

// ---------------- launcher ---------------------------------------------------
extern "C" void kernel_launch(void* const* d_in, const int* in_sizes, int n_in,
                              void* d_out, int out_size) {
    const float* x = (const float*)d_in[0];
    const float* conv_w = (const float*)d_in[1];
    const float* conv_b = (const float*)d_in[2];
    const float* loc_w = (const float*)d_in[3];
    const float* loc_b = (const float*)d_in[4];
    const float* cls_w = (const float*)d_in[5];
    const float* cls_b = (const float*)d_in[6];
    const int* imh = (const int*)d_in[7];
    const int* imw = (const int*)d_in[8];
    float* out = (float*)d_out;

    cudaFuncSetAttribute(conv3x3_kernel,
                         cudaFuncAttributeMaxDynamicSharedMemorySize, CONV_SMEM);

    wtrans_kernel<<<(CIN * CIN * 9 + 255) / 256, 256>>>(conv_w);
    conv3x3_kernel<<<dim3(8, 16, 8), 256, CONV_SMEM>>>(x, conv_b);
    heads_kernel<<<256, 128>>>(loc_w, loc_b, cls_w, cls_b, imh, imw, out);

    sort_phase1_kernel<<<128, 1024>>>();
    for (int k = 8192; k <= NSORT; k <<= 1) {
        for (int j = k >> 1; j >= TILE; j >>= 1)
            sort_gstep_kernel<<<(BB * NSORT) / 256, 256>>>(k, j);
        sort_sphase_kernel<<<128, 1024>>>(k);
    }

    nms_kernel<<<8, 256>>>(out);
}

// round 15
// speedup vs baseline: 1.9580x; 1.9580x over previous
#include <cuda_runtime.h>
#include <math.h>
#include <cstdint>

#define BB 8
#define CIN 512
#define HH 64
#define WW 64
#define HWP 4096          // 64*64
#define NA 36864          // anchors per batch = 4096*9
#define NSORT 65536
#define NPRE 6000
#define NPOST 300

// output layout (floats)
#define OFF_CLS 0ull
#define OFF_LOC 589824ull
#define OFF_ROI 1769472ull
#define OFF_IDX 1779072ull

#define NEGINF (__int_as_float(0xff800000))

typedef unsigned long long ull;

// ---------------- packed f32x2 helpers (bitwise-identical IEEE fp32) ---------
__device__ __forceinline__ ull pack2(float x, float y) {
    ull r;
    asm("mov.b64 %0, {%1, %2};" : "=l"(r) : "f"(x), "f"(y));
    return r;
}
__device__ __forceinline__ float2 unpack2(ull v) {
    float2 r;
    asm("mov.b64 {%0, %1}, %2;" : "=f"(r.x), "=f"(r.y) : "l"(v));
    return r;
}
__device__ __forceinline__ void ffma2(ull& d, ull a, ull b) {
    asm("fma.rn.f32x2 %0, %1, %2, %0;" : "+l"(d) : "l"(a), "l"(b));
}

__device__ __forceinline__ uint32_t smem_u32(const void* p) {
    uint32_t a;
    asm("{ .reg .u64 t; cvta.to.shared.u64 t, %1; cvt.u32.u64 %0, t; }"
        : "=r"(a) : "l"(p));
    return a;
}
#define CP_COMMIT() asm volatile("cp.async.commit_group;" ::: "memory")
#define CP_WAIT1()  asm volatile("cp.async.wait_group 1;" ::: "memory")
#define CP_WAIT0()  asm volatile("cp.async.wait_group 0;" ::: "memory")

__device__ __forceinline__ void cp4(uint32_t dst, const float* src, bool ok) {
    asm volatile("cp.async.ca.shared.global [%0], [%1], 4, %2;"
                 :: "r"(dst), "l"(src), "r"(ok ? 4u : 0u) : "memory");
}

// ---------------- scratch (static device globals; no allocation) -------------
static __device__ float g_h[(size_t)BB * CIN * HWP];            // 64 MB conv output
static __device__ float g_wt[(size_t)CIN * 9 * CIN];            // transposed conv weights
static __device__ float g_roi[(size_t)BB * NA * 4];             // clipped boxes
static __device__ float g_score[(size_t)BB * NA];               // scores (-inf if invalid)
static __device__ ull g_keys[(size_t)BB * NSORT];               // sort keys (padded)

// anchor base half-heights / half-widths (float32 of the np.float64 math)
__constant__ float c_h2[9] = {
    45.254833995939045f, 90.50966799187809f, 181.01933598375618f,
    64.0f, 128.0f, 256.0f,
    90.50966799187809f, 181.01933598375618f, 362.03867196751236f};
__constant__ float c_w2[9] = {
    90.50966799187809f, 181.01933598375618f, 362.03867196751236f,
    64.0f, 128.0f, 256.0f,
    45.254833995939045f, 90.50966799187809f, 181.01933598375618f};

// ---------------- 0: weight transpose  [oc][ic][3][3] -> [ic][k][oc] ---------
__global__ void wtrans_kernel(const float* __restrict__ w) {
    int idx = blockIdx.x * blockDim.x + threadIdx.x;
    if (idx >= CIN * CIN * 9) return;
    int kk = idx % 9;
    int ic = (idx / 9) % CIN;
    int oc = idx / (9 * CIN);
    g_wt[((size_t)ic * 9 + kk) * CIN + oc] = w[idx];
}

// ---------------- 1: 3x3 conv + bias + relu (R13, proven 6202us) ------------
#define IN_WORDS (8 * 6 * 68)          // 3264 (66 used cols, stride 68 for 16B)
#define W_WORDS (8 * 9 * 64)           // 4608
#define BUF_WORDS (IN_WORDS + W_WORDS) // 7872
#define CONV_SMEM (2 * BUF_WORDS * 4)  // 62976 bytes

__global__ __launch_bounds__(256, 2) void conv3x3_kernel(
    const float* __restrict__ x, const float* __restrict__ bias) {
    extern __shared__ float sm[];
    const int octile = blockIdx.x;   // 0..7   (oc base = octile*64)
    const int y0 = blockIdx.y * 4;   // rows y0..y0+3
    const int b = blockIdx.z;        // 0..7
    const int tid = threadIdx.x;
    const int lane = tid & 31;
    const int ty = tid >> 5;         // warp id = oc subgroup 0..7
    const int r_out = lane >> 3;     // 0..3 row within block
    const int X0 = (lane & 7) * 8;   // x base, 8 px per thread

    const float* xb = x + (size_t)b * CIN * HWP;

    // stage chunk (8 input channels starting at icg) into buffer buf
    auto stage = [&](int buf, int icg) {
        float* s_in = sm + buf * BUF_WORDS;
        float* s_wt = s_in + IN_WORDS;
        // inputs: 48 halo'd rows (8 ic x 6 rows) x 66 cols. Warp ty owns rows
        // ty, ty+8, ..., ty+40. Lane covers cols lane, lane+32, (lane<2: +64).
#pragma unroll
        for (int j = 0; j < 6; j++) {
            int row = ty + 8 * j;        // 0..47
            int ic = row / 6;            // const-div (mul-shift)
            int r = row - ic * 6;        // 0..5
            int gy = y0 + r - 1;
            bool rowok = ((unsigned)gy < 64u);
            const float* srow = xb + (size_t)(icg + ic) * HWP + gy * 64;
            uint32_t drow = smem_u32(&s_in[(ic * 6 + r) * 68]);
            {
                int gx = lane - 1;                       // xx = lane
                bool ok = rowok && (gx >= 0);
                cp4(drow + lane * 4, ok ? (srow + gx) : xb, ok);
            }
            {
                int gx = lane + 31;                      // xx = lane+32 (<64 always)
                cp4(drow + (lane + 32) * 4, rowok ? (srow + gx) : xb, rowok);
            }
            if (lane < 2) {
                int gx = lane + 63;                      // xx = lane+64
                bool ok = rowok && (gx < 64);
                cp4(drow + (lane + 64) * 4, ok ? (srow + gx) : xb, ok);
            }
        }
        // weights: 8 ic x 9 taps x 64 oc via 16B cp.async (1152 chunks)
        const float* wsrc = g_wt + (size_t)icg * 9 * CIN + octile * 64;
#pragma unroll
        for (int j = 0; j < 5; j++) {
            int t = tid + j * 256;
            if (t < 1152) {
                int c4 = t & 15;
                int kk = (t >> 4) % 9;
                int ic = t / 144;
                const float* src = wsrc + (size_t)(ic * 9 + kk) * CIN + c4 * 4;
                uint32_t dst = smem_u32(&s_wt[(ic * 9 + kk) * 64 + c4 * 4]);
                asm volatile("cp.async.cg.shared.global [%0], [%1], 16;"
                             :: "r"(dst), "l"(src) : "memory");
            }
        }
    };

    // acc2[g][i]: packed (acc[oc=2g], acc[oc=2g+1]) for px i
    ull acc2[4][8];
#pragma unroll
    for (int g = 0; g < 4; g++)
#pragma unroll
        for (int i = 0; i < 8; i++) acc2[g][i] = pack2(0.f, 0.f);

    stage(0, 0);
    CP_COMMIT();

    for (int s = 0; s < 64; s++) {
        if (s + 1 < 64) {
            stage((s + 1) & 1, (s + 1) * 8);
            CP_COMMIT();
            CP_WAIT1();
        } else {
            CP_WAIT0();
        }
        __syncthreads();

        const float* s_in = sm + (s & 1) * BUF_WORDS;
        const float* s_wt = s_in + IN_WORDS;

#pragma unroll
        for (int ic = 0; ic < 8; ic++) {
#pragma unroll
            for (int ky = 0; ky < 3; ky++) {
                // 10 input cols X0..X0+9 (row stride 68 words = 16B aligned)
                const float* irow = &s_in[(ic * 6 + r_out + ky) * 68 + X0];
                float4 f0 = *(const float4*)(irow);
                float4 f1 = *(const float4*)(irow + 4);
                float2 f2 = *(const float2*)(irow + 8);
                ull xp[10];
                xp[0] = pack2(f0.x, f0.x); xp[1] = pack2(f0.y, f0.y);
                xp[2] = pack2(f0.z, f0.z); xp[3] = pack2(f0.w, f0.w);
                xp[4] = pack2(f1.x, f1.x); xp[5] = pack2(f1.y, f1.y);
                xp[6] = pack2(f1.z, f1.z); xp[7] = pack2(f1.w, f1.w);
                xp[8] = pack2(f2.x, f2.x); xp[9] = pack2(f2.y, f2.y);
#pragma unroll
                for (int kx = 0; kx < 3; kx++) {
                    // 8 oc weights via two 128-bit loads (warp-uniform addr)
                    const ulonglong2* wp =
                        (const ulonglong2*)&s_wt[(ic * 9 + ky * 3 + kx) * 64 + ty * 8];
                    ulonglong2 wv0 = wp[0];
                    ulonglong2 wv1 = wp[1];
#pragma unroll
                    for (int i = 0; i < 8; i++) {
                        ffma2(acc2[0][i], xp[i + kx], wv0.x);
                        ffma2(acc2[1][i], xp[i + kx], wv0.y);
                        ffma2(acc2[2][i], xp[i + kx], wv1.x);
                        ffma2(acc2[3][i], xp[i + kx], wv1.y);
                    }
                }
            }
        }
        __syncthreads();
    }

    const int ocbase = octile * 64 + ty * 8;
    const int yrow = y0 + r_out;
#pragma unroll
    for (int g = 0; g < 4; g++) {
        float bv0 = bias[ocbase + 2 * g];
        float bv1 = bias[ocbase + 2 * g + 1];
        float r0[8], r1[8];
#pragma unroll
        for (int i = 0; i < 8; i++) {
            float2 u = unpack2(acc2[g][i]);
            r0[i] = fmaxf(u.x + bv0, 0.f);
            r1[i] = fmaxf(u.y + bv1, 0.f);
        }
        float* d0 = &g_h[((size_t)(b * CIN + ocbase + 2 * g)) * HWP + yrow * WW + X0];
        float* d1 = &g_h[((size_t)(b * CIN + ocbase + 2 * g + 1)) * HWP + yrow * WW + X0];
        *(float4*)(d0)     = make_float4(r0[0], r0[1], r0[2], r0[3]);
        *(float4*)(d0 + 4) = make_float4(r0[4], r0[5], r0[6], r0[7]);
        *(float4*)(d1)     = make_float4(r1[0], r1[1], r1[2], r1[3]);
        *(float4*)(d1 + 4) = make_float4(r1[4], r1[5], r1[6], r1[7]);
    }
}

// ---------------- 2: heads (1x1 convs) + proposal prep -----------------------
__global__ __launch_bounds__(128) void heads_kernel(
    const float* __restrict__ loc_w, const float* __restrict__ loc_b,
    const float* __restrict__ cls_w, const float* __restrict__ cls_b,
    const int* __restrict__ imh, const int* __restrict__ imw,
    float* __restrict__ out) {
    const int b = blockIdx.x >> 5;
    const int p = ((blockIdx.x & 31) << 7) + threadIdx.x;  // 0..4095

    __shared__ float s_w[64][56];  // padded to 56 for 8B alignment of pairs

    ull acc2[27];
#pragma unroll
    for (int m = 0; m < 27; m++) acc2[m] = pack2(0.f, 0.f);

    const float* hb = g_h + (size_t)b * CIN * HWP + p;

    for (int icg = 0; icg < CIN; icg += 64) {
        __syncthreads();
        for (int t = threadIdx.x; t < 64 * 54; t += 128) {
            int m = t % 54;
            int ic = t / 54;
            float wv = (m < 36) ? loc_w[m * CIN + icg + ic]
                                : cls_w[(m - 36) * CIN + icg + ic];
            s_w[ic][m] = wv;
        }
        __syncthreads();
        for (int ic = 0; ic < 64; ic++) {
            float hv = hb[(size_t)(icg + ic) * HWP];
            ull hp = pack2(hv, hv);
            const ull* wrow = (const ull*)&s_w[ic][0];
#pragma unroll
            for (int m = 0; m < 27; m++) ffma2(acc2[m], hp, wrow[m]);
        }
    }

    float acc[54];
#pragma unroll
    for (int m = 0; m < 27; m++) {
        float2 u = unpack2(acc2[m]);
        acc[2 * m] = u.x;
        acc[2 * m + 1] = u.y;
    }

    const float fh = (float)(*imh);
    const float fw = (float)(*imw);
    const int py = p >> 6, px = p & 63;
    const float sy = (float)py * 16.0f;
    const float sx = (float)px * 16.0f;

    const size_t cls_base = OFF_CLS + ((size_t)b * NA + (size_t)p * 9) * 2;
    const size_t loc_base = OFF_LOC + ((size_t)b * NA + (size_t)p * 9) * 4;

#pragma unroll
    for (int a = 0; a < 9; a++) {
        float dy = acc[4 * a + 0] + loc_b[4 * a + 0];
        float dx = acc[4 * a + 1] + loc_b[4 * a + 1];
        float dh = acc[4 * a + 2] + loc_b[4 * a + 2];
        float dw = acc[4 * a + 3] + loc_b[4 * a + 3];
        out[loc_base + a * 4 + 0] = dy;
        out[loc_base + a * 4 + 1] = dx;
        out[loc_base + a * 4 + 2] = dh;
        out[loc_base + a * 4 + 3] = dw;

        float v0 = acc[36 + 2 * a + 0] + cls_b[2 * a + 0];
        float v1 = acc[36 + 2 * a + 1] + cls_b[2 * a + 1];
        float c0 = 1.f / (1.f + expf(-v0));
        float c1 = 1.f / (1.f + expf(-v1));
        out[cls_base + a * 2 + 0] = c0;
        out[cls_base + a * 2 + 1] = c1;

        // anchor decode + clip + min-size filter
        float a0 = -c_h2[a] + sy;
        float a1 = -c_w2[a] + sx;
        float a2 = c_h2[a] + sy;
        float a3 = c_w2[a] + sx;
        float hh = a2 - a0;
        float ww = a3 - a1;
        float cy = a0 + 0.5f * hh;
        float cx = a1 + 0.5f * ww;
        cy = cy + dy * hh;
        cx = cx + dx * ww;
        hh = hh * expf(dh);
        ww = ww * expf(dw);
        float r0 = cy - 0.5f * hh;
        float r1 = cx - 0.5f * ww;
        float r2 = cy + 0.5f * hh;
        float r3 = cx + 0.5f * ww;
        r0 = fminf(fmaxf(r0, 0.f), fh);
        r1 = fminf(fmaxf(r1, 0.f), fw);
        r2 = fminf(fmaxf(r2, 0.f), fh);
        r3 = fminf(fmaxf(r3, 0.f), fw);
        float hs = r2 - r0;
        float ws = r3 - r1;
        bool valid = (hs >= 16.0f) && (ws >= 16.0f);
        float sc = valid ? c1 : NEGINF;

        int i = p * 9 + a;
        float4 rb;
        rb.x = r0; rb.y = r1; rb.z = r2; rb.w = r3;
        *(float4*)&g_roi[((size_t)b * NA + i) * 4] = rb;
        g_score[(size_t)b * NA + i] = sc;
        unsigned uu = __float_as_uint(sc);
        uu = (uu & 0x80000000u) ? ~uu : (uu | 0x80000000u);
        g_keys[(size_t)b * NSORT + i] =
            ((ull)uu << 32) | (unsigned)(0xFFFFFFFFu - (unsigned)i);
    }
    // padding keys (7 per thread: 4096*7 = 28672 = 65536-36864)
#pragma unroll
    for (int k2 = 0; k2 < 7; k2++)
        g_keys[(size_t)b * NSORT + NA + p * 7 + k2] = 0ull;
}

// ---------------- 3: bitonic sort, smem-tiled --------------------------------
#define TILE 4096

__global__ __launch_bounds__(1024) void sort_phase1_kernel() {
    __shared__ ull s[TILE];
    const int batch = blockIdx.x >> 4;
    const int tile = blockIdx.x & 15;
    ull* d = g_keys + (size_t)batch * NSORT + (size_t)tile * TILE;
    const int gbase = tile * TILE;

    for (int t = threadIdx.x; t < TILE; t += 1024) s[t] = d[t];
    __syncthreads();

    for (int k = 2; k <= TILE; k <<= 1) {
        for (int j = k >> 1; j > 0; j >>= 1) {
            for (int t = threadIdx.x; t < TILE; t += 1024) {
                int ixj = t ^ j;
                if (ixj > t) {
                    ull A = s[t];
                    ull Bv = s[ixj];
                    bool up = (((gbase + t) & k) == 0);
                    if (up ? (A > Bv) : (A < Bv)) {
                        s[t] = Bv;
                        s[ixj] = A;
                    }
                }
            }
            __syncthreads();
        }
    }
    for (int t = threadIdx.x; t < TILE; t += 1024) d[t] = s[t];
}

__global__ __launch_bounds__(256) void sort_gstep_kernel(int k, int j) {
    int idx = blockIdx.x * blockDim.x + threadIdx.x;
    int b = idx >> 16;
    int t = idx & (NSORT - 1);
    ull* d = g_keys + (size_t)b * NSORT;
    int ixj = t ^ j;
    if (ixj > t) {
        ull A = d[t];
        ull Bv = d[ixj];
        bool up = ((t & k) == 0);
        if (up ? (A > Bv) : (A < Bv)) {
            d[t] = Bv;
            d[ixj] = A;
        }
    }
}

__global__ __launch_bounds__(1024) void sort_sphase_kernel(int k) {
    __shared__ ull s[TILE];
    const int batch = blockIdx.x >> 4;
    const int tile = blockIdx.x & 15;
    ull* d = g_keys + (size_t)batch * NSORT + (size_t)tile * TILE;
    const int gbase = tile * TILE;

    for (int t = threadIdx.x; t < TILE; t += 1024) s[t] = d[t];
    __syncthreads();

    for (int j = TILE / 2; j > 0; j >>= 1) {
        for (int t = threadIdx.x; t < TILE; t += 1024) {
            int ixj = t ^ j;
            if (ixj > t) {
                ull A = s[t];
                ull Bv = s[ixj];
                bool up = (((gbase + t) & k) == 0);
                if (up ? (A > Bv) : (A < Bv)) {
                    s[t] = Bv;
                    s[ixj] = A;
                }
            }
        }
        __syncthreads();
    }
    for (int t = threadIdx.x; t < TILE; t += 1024) d[t] = s[t];
}

// ---------------- 4: per-batch NMS, fully smem-resident ----------------------
// Boxes (96KB) + scores (24KB) + mask (6KB) live in dynamic smem: the
// suppression loop's 6000x300 box reads become 29-cyc LDS instead of ~234-cyc
// L2 hits. Identical values, identical iteration order -> bit-identical picks.
#define NMS_SMEM (NPRE * 16 + NPRE * 4 + NPRE + 64)

__global__ __launch_bounds__(512) void nms_kernel(float* __restrict__ out) {
    extern __shared__ char nsm[];
    float4* sbox = (float4*)nsm;                       // 96000 B
    float* ss = (float*)(nsm + NPRE * 16);             // 24000 B
    unsigned char* smask = (unsigned char*)(nsm + NPRE * 20);  // 6000 B
    int* s_pick = (int*)(nsm + NPRE * 21 + 8);

    const int b = blockIdx.x;
    const ull* kb = g_keys + (size_t)b * NSORT;

    // gather top-6000 (descending = from the top of ascending sort)
    for (int t = threadIdx.x; t < NPRE; t += blockDim.x) {
        ull key = kb[NSORT - 1 - t];
        unsigned ai = 0xFFFFFFFFu - (unsigned)(key & 0xFFFFFFFFull);
        sbox[t] = *(const float4*)&g_roi[((size_t)b * NA + ai) * 4];
        ss[t] = g_score[(size_t)b * NA + ai];
        smask[t] = 0;
    }
    for (int t = threadIdx.x; t < NPOST; t += blockDim.x)
        out[OFF_IDX + (size_t)b * NPOST + t] = (float)b;
    __syncthreads();

    int ptr = 0;  // meaningful on thread 0 only
    for (int pick = 0; pick < NPOST; pick++) {
        if (threadIdx.x == 0) {
            while (ptr < NPRE && smask[ptr]) ptr++;
            if (ptr < NPRE && ss[ptr] != NEGINF) {
                *s_pick = ptr;
                smask[ptr] = 1;
            } else {
                *s_pick = -1;
            }
        }
        __syncthreads();
        int p = *s_pick;
        __syncthreads();
        if (p < 0) {
            int rem = (NPOST - pick) * 4;
            for (int t = threadIdx.x; t < rem; t += blockDim.x)
                out[OFF_ROI + ((size_t)b * NPOST + pick) * 4 + t] = 0.f;
            break;
        }
        float4 pb = sbox[p];
        if (threadIdx.x == 0) {
            out[OFF_ROI + ((size_t)b * NPOST + pick) * 4 + 0] = pb.x;
            out[OFF_ROI + ((size_t)b * NPOST + pick) * 4 + 1] = pb.y;
            out[OFF_ROI + ((size_t)b * NPOST + pick) * 4 + 2] = pb.z;
            out[OFF_ROI + ((size_t)b * NPOST + pick) * 4 + 3] = pb.w;
        }
        float parea = (pb.z - pb.x) * (pb.w - pb.y);
        for (int j = p + 1 + threadIdx.x; j < NPRE; j += blockDim.x) {
            if (!smask[j]) {
                float4 q = sbox[j];
                float yy1 = fmaxf(q.x, pb.x);
                float xx1 = fmaxf(q.y, pb.y);
                float yy2 = fminf(q.z, pb.z);
                float xx2 = fminf(q.w, pb.w);
                float inter = fmaxf(yy2 - yy1, 0.f) * fmaxf(xx2 - xx1, 0.f);
                float qarea = (q.z - q.x) * (q.w - q.y);
                float iou = inter / (qarea + parea - inter + 1e-9f);
                if (iou > 0.7f) smask[j] = 1;
            }
        }
        __syncthreads();
    }
}

// ---------------- launcher ---------------------------------------------------
extern "C" void kernel_launch(void* const* d_in, const int* in_sizes, int n_in,
                              void* d_out, int out_size) {
    const float* x = (const float*)d_in[0];
    const float* conv_w = (const float*)d_in[1];
    const float* conv_b = (const float*)d_in[2];
    const float* loc_w = (const float*)d_in[3];
    const float* loc_b = (const float*)d_in[4];
    const float* cls_w = (const float*)d_in[5];
    const float* cls_b = (const float*)d_in[6];
    const int* imh = (const int*)d_in[7];
    const int* imw = (const int*)d_in[8];
    float* out = (float*)d_out;

    cudaFuncSetAttribute(conv3x3_kernel,
                         cudaFuncAttributeMaxDynamicSharedMemorySize, CONV_SMEM);
    cudaFuncSetAttribute(nms_kernel,
                         cudaFuncAttributeMaxDynamicSharedMemorySize, NMS_SMEM);

    wtrans_kernel<<<(CIN * CIN * 9 + 255) / 256, 256>>>(conv_w);
    conv3x3_kernel<<<dim3(8, 16, 8), 256, CONV_SMEM>>>(x, conv_b);
    heads_kernel<<<256, 128>>>(loc_w, loc_b, cls_w, cls_b, imh, imw, out);

    sort_phase1_kernel<<<128, 1024>>>();
    for (int k = 8192; k <= NSORT; k <<= 1) {
        for (int j = k >> 1; j >= TILE; j >>= 1)
            sort_gstep_kernel<<<(BB * NSORT) / 256, 256>>>(k, j);
        sort_sphase_kernel<<<128, 1024>>>(k);
    }

    nms_kernel<<<8, 512, NMS_SMEM>>>(out);
}